// round 9
// baseline (speedup 1.0000x reference)
#include <cuda_runtime.h>
#include <cuda_fp16.h>
#include <math.h>
#include <cstdint>

// ============================================================================
// Round 9: out = s_in @ Wfold + bfold (algebraic collapse, R2 derivation).
// fp16 m16n8k16, persistent warp-autonomous kernel.
//  - 16-row batches (NB=6250): kills the 2-vs-1 batch quantization (66%->88%)
//  - 3 CTAs/SM (64.3 KB smem), 24 warps/SM
//  - PDL: mma launches early, A-prologue overlaps prep; griddepcontrol.wait
//    before touching folded W. Counter reset via cudaMemsetAsync before prep.
// ============================================================================

#define EPS_F 1e-6f

__device__ __half g_Wh[16384];    // fragment-major f16 W (256k x 64n)
__device__ float g_bf[64];
__device__ int g_ctr;

// ---------------- prep: fold Wv over heads, f16-round, scatter --------------
// actual k = c*16 + kq*4 + s*2 + w  <->  hw col (kq*2 + s*8 + w) of step c
__global__ void prep_kernel(const float* __restrict__ Wv,
                            const float* __restrict__ bv, float nf) {
    asm volatile("griddepcontrol.launch_dependents;");
    const float scale = nf / (8.f * (nf + EPS_F));
    const int t = threadIdx.x;                 // 256
    const int k = blockIdx.x * 4 + (t >> 6);   // 0..255
    const int n = t & 63;

    float s = 0.f;
#pragma unroll
    for (int h = 0; h < 8; h++) s += Wv[k * 512 + h * 64 + n];
    float wf = s * scale;

    const int c  = k >> 4;
    const int r  = k & 15;
    const int kq = r >> 2;
    const int s2 = (r >> 1) & 1;
    const int w  = k & 1;
    const int j  = n >> 3;
    const int nn = n & 7;
    const int lane = nn * 4 + kq;
    g_Wh[((((c * 8 + j) * 32) + lane) * 2 + s2) * 2 + w] = __float2half_rn(wf);

    if (k == 0) {
        float b = 0.f;
#pragma unroll
        for (int h = 0; h < 8; h++) b += bv[h * 64 + n];
        g_bf[n] = b * scale;
    }
}

// ---------------- helpers ---------------------------------------------------
#define PACK_F16X2(d, hi, lo) \
    asm("cvt.rn.f16x2.f32 %0, %1, %2;" : "=r"(d) : "f"(hi), "f"(lo))

#define MMA_F16(c, a0, a1, a2, a3, b0, b1)                                      \
    asm volatile(                                                               \
        "mma.sync.aligned.m16n8k16.row.col.f32.f16.f16.f32 "                    \
        "{%0,%1,%2,%3}, {%4,%5,%6,%7}, {%8,%9}, {%0,%1,%2,%3};"                 \
        : "+f"((c)[0]), "+f"((c)[1]), "+f"((c)[2]), "+f"((c)[3])                \
        : "r"(a0), "r"(a1), "r"(a2), "r"(a3), "r"(b0), "r"(b1))

#define CP_ASYNC16(dst, src)                                                    \
    asm volatile("cp.async.cg.shared.global [%0], [%1], 16;"                    \
                 :: "r"(dst), "l"(src) : "memory")
#define CP_COMMIT()  asm volatile("cp.async.commit_group;" ::: "memory")
#define CP_WAIT(n)   asm volatile("cp.async.wait_group %0;" :: "n"(n) : "memory")

__device__ __forceinline__ uint32_t smem_u32(const void* p) {
    uint32_t a;
    asm("{ .reg .u64 t; cvta.to.shared.u64 t, %1; cvt.u32.u64 %0, t; }"
        : "=r"(a) : "l"(p));
    return a;
}

// smem u32 layout: [0..8191] W frags | [8192..8255] bias | rings 1KB/warp/stage
#define RING0_U32 8256
#define SMEM_U32  (RING0_U32 + 8 * 1024)    // 16448 u32 = 65792 B

// ---------------- main persistent GEMM: [M,256] @ [256,64] ------------------
// 16 rows per warp-batch, one m16n64 tile; 4-stage cp.async ring.
__global__ __launch_bounds__(256, 3)
void mma_gemm(const float* __restrict__ A, float* __restrict__ C,
              int M, int NB) {
    extern __shared__ uint32_t sm[];
    const uint32_t sb = smem_u32(sm);

    const int t = threadIdx.x;
    const int wid = t >> 5;
    const int lane = t & 31;
    const int g  = lane >> 2;
    const int kq = lane & 3;

    // ring: 4 stages x 1024 B per warp; thread slot = row*64 + kq*16
    const uint32_t ring0 = sb + RING0_U32 * 4 + wid * 4096 + g * 64 + kq * 16;
    const float4* ringp = (const float4*)((const char*)sm +
                          RING0_U32 * 4 + wid * 4096 + g * 64 + kq * 16);
    // ringp in float4 units: stage*64 (1KB) ; +32 for row g+8

#define SETUP_PTRS(p0, p1, base)                                                \
    const float* p0 = A + (size_t)min((base) + g,     M - 1) * 256 + kq * 4;    \
    const float* p1 = A + (size_t)min((base) + g + 8, M - 1) * 256 + kq * 4

#define LOAD_CHUNK(p0, p1, c, st) do {                                          \
        uint32_t d_ = ring0 + (st) * 1024;                                      \
        CP_ASYNC16(d_,       p0 + (c) * 16);                                    \
        CP_ASYNC16(d_ + 512, p1 + (c) * 16);                                    \
    } while (0)

    // ---- grab first batch + A prologue (independent of prep) ----
    int b;
    if (lane == 0) b = atomicAdd(&g_ctr, 1);
    b = __shfl_sync(0xffffffffu, b, 0);
    const bool have = (b < NB);

    if (have) {
        SETUP_PTRS(i0, i1, b * 16);
        LOAD_CHUNK(i0, i1, 0, 0); CP_COMMIT();
        LOAD_CHUNK(i0, i1, 1, 1); CP_COMMIT();
        LOAD_CHUNK(i0, i1, 2, 2); CP_COMMIT();
    } else {
        CP_COMMIT(); CP_COMMIT(); CP_COMMIT();
    }

    // ---- wait for prep's W, then stage it (32 KB, hits L2) ----
    asm volatile("griddepcontrol.wait;");
    {
        uint32_t dst = sb + t * 16;
        const char* src = (const char*)g_Wh + t * 16;
#pragma unroll
        for (int i = 0; i < 8; i++)
            CP_ASYNC16(dst + i * 4096, src + i * 4096);
        CP_COMMIT();
    }
    if (t < 64) ((float*)(sm + 8192))[t] = g_bf[t];
    CP_WAIT(0);
    __syncthreads();

    const uint2* Wp = ((const uint2*)sm) + lane;
    const float* bias_s = (const float*)(sm + 8192);

    if (have) {
        SETUP_PTRS(s0, s1, b * 16);
        const float *c0p = s0, *c1p = s1;

        for (;;) {
            int bn = NB;
            const float *n0p = c0p, *n1p = c1p;

            float acc[8][4];
#pragma unroll
            for (int j = 0; j < 8; j++)
#pragma unroll
                for (int i = 0; i < 4; i++) acc[j][i] = 0.f;

#pragma unroll
            for (int c = 0; c < 16; c++) {
                if (c == 12) {
                    if (lane == 0) bn = atomicAdd(&g_ctr, 1);
                    bn = __shfl_sync(0xffffffffu, bn, 0);
                }
                if (c == 13 && bn < NB) {
                    SETUP_PTRS(t0, t1, bn * 16);
                    n0p = t0; n1p = t1;
                }
                if (c < 13) {
                    LOAD_CHUNK(c0p, c1p, c + 3, (c + 3) & 3);
                } else if (bn < NB) {
                    LOAD_CHUNK(n0p, n1p, c - 13, (c + 3) & 3);
                }
                CP_COMMIT();
                CP_WAIT(3);

                const int st = c & 3;
                float4 q0 = ringp[st * 64];
                float4 q1 = ringp[st * 64 + 32];

                uint32_t a0, a1, a2, a3;
                PACK_F16X2(a0, q0.y, q0.x); PACK_F16X2(a1, q1.y, q1.x);
                PACK_F16X2(a2, q0.w, q0.z); PACK_F16X2(a3, q1.w, q1.z);
#pragma unroll
                for (int j = 0; j < 8; j++) {
                    uint2 w2 = Wp[(c * 8 + j) * 32];
                    MMA_F16(acc[j], a0, a1, a2, a3, w2.x, w2.y);
                }
            }

            // epilogue: bias + store (rows b*16+g, +8; cols j*8 + kq*2, +1)
            const int r0 = b * 16 + g;
            const int r1 = r0 + 8;
#pragma unroll
            for (int j = 0; j < 8; j++) {
                int col = j * 8 + kq * 2;
                float2 bb = *(const float2*)(bias_s + col);
                if (r0 < M)
                    *(float2*)(C + (size_t)r0 * 64 + col) =
                        make_float2(acc[j][0] + bb.x, acc[j][1] + bb.y);
                if (r1 < M)
                    *(float2*)(C + (size_t)r1 * 64 + col) =
                        make_float2(acc[j][2] + bb.x, acc[j][3] + bb.y);
            }

            if (bn >= NB) break;
            b = bn;
            c0p = n0p; c1p = n1p;
        }
    }
#undef LOAD_CHUNK
#undef SETUP_PTRS
}

// ---------------- launch ----------------------------------------------------
extern "C" void kernel_launch(void* const* d_in, const int* in_sizes, int n_in,
                              void* d_out, int out_size) {
    const float* s_in = (const float*)d_in[1];
    const float* Wv   = (const float*)d_in[6];
    const float* bv   = (const float*)d_in[7];
    float* out = (float*)d_out;

    const int M = in_sizes[0] / 256;
    const int NB = (M + 15) / 16;

    // reset work counter (graph-capturable memset; ordered before prep & mma)
    void* pCtr;
    cudaGetSymbolAddress(&pCtr, g_ctr);
    cudaMemsetAsync(pCtr, 0, sizeof(int));

    prep_kernel<<<64, 256>>>(Wv, bv, (float)M);

    const int SMEM = SMEM_U32 * 4;   // 65792 B -> 3 CTAs/SM
    cudaFuncSetAttribute(mma_gemm,
                         cudaFuncAttributeMaxDynamicSharedMemorySize, SMEM);

    // PDL launch: mma may start while prep runs; it waits via griddepcontrol
    cudaLaunchConfig_t cfg = {};
    cfg.gridDim = dim3(444, 1, 1);
    cfg.blockDim = dim3(256, 1, 1);
    cfg.dynamicSmemBytes = SMEM;
    cudaLaunchAttribute attrs[1];
    attrs[0].id = cudaLaunchAttributeProgrammaticStreamSerialization;
    attrs[0].val.programmaticStreamSerializationAllowed = 1;
    cfg.attrs = attrs;
    cfg.numAttrs = 1;
    cudaLaunchKernelEx(&cfg, mma_gemm, s_in, out, M, NB);
}